// round 9
// baseline (speedup 1.0000x reference)
#include <cuda_runtime.h>
#include <math.h>

#define D    128
#define HC   128
#define TD   32
#define MD   64
#define AD   96    // TD + MD
#define NMAX 50048
#define EMAX 500224
#define CHUNK 128  // sorted positions per warp

// scratch (static device memory — no allocations allowed)
__device__ float g_q[NMAX * HC];
__device__ float g_k[NMAX * HC];
__device__ float g_v[NMAX * HC];
__device__ float g_sk[NMAX * HC];
__device__ float g_mq[NMAX * 2 * AD];    // per-head We^T q
__device__ float g_accA[NMAX * 2 * AD];  // sum_e w_h * attr
__device__ float g_den[NMAX * 2];
__device__ int   g_cnt[NMAX];
__device__ int   g_cur[NMAX];
__device__ int4  g_es[EMAX];             // sorted (src, dst, time, eid)
__device__ int   g_bsum[64];

typedef unsigned long long ull;

__device__ __forceinline__ ull pack2(float lo, float hi) {
    ull r; asm("mov.b64 %0, {%1, %2};" : "=l"(r) : "f"(lo), "f"(hi)); return r;
}
__device__ __forceinline__ void unpack2(ull v, float& lo, float& hi) {
    asm("mov.b64 {%0, %1}, %2;" : "=f"(lo), "=f"(hi) : "l"(v));
}
__device__ __forceinline__ ull ffma2(ull a, ull b, ull c) {
    ull d; asm("fma.rn.f32x2 %0, %1, %2, %3;" : "=l"(d) : "l"(a), "l"(b), "l"(c)); return d;
}
__device__ __forceinline__ void red_add_v4(float* addr, float4 v) {
    asm volatile("red.global.add.v4.f32 [%0], {%1,%2,%3,%4};"
                 :: "l"(addr), "f"(v.x), "f"(v.y), "f"(v.z), "f"(v.w) : "memory");
}

// ---------------------------------------------------------------------------
// K0: zero accA + cnt
// ---------------------------------------------------------------------------
__global__ void zero_kernel(int n) {
    int i = blockIdx.x * blockDim.x + threadIdx.x;
    if (i < n * 2 * AD) g_accA[i] = 0.0f;
    if (i < n)          g_cnt[i] = 0;
}

// ---------------------------------------------------------------------------
// K1: fused node projections  q/k/v/skip = x @ W + b   (+ zero out/den)
// ---------------------------------------------------------------------------
__global__ __launch_bounds__(128) void proj_kernel(
    const float* __restrict__ x,
    const float* __restrict__ Wq, const float* __restrict__ bq,
    const float* __restrict__ Wk, const float* __restrict__ bk,
    const float* __restrict__ Wv, const float* __restrict__ bv,
    const float* __restrict__ Ws, const float* __restrict__ bs,
    float* __restrict__ out, int n)
{
    __shared__ __align__(16) float2 xs2[D][9];
    const int r0 = blockIdx.x * 16;
    const int c  = threadIdx.x;

    #pragma unroll
    for (int r = 0; r < 16; r++) {
        const int row = r0 + r;
        if (row < n) {
            out[(size_t)row * HC + c] = 0.0f;
            if (c < 2) g_den[row * 2 + c] = 0.0f;
        }
    }
    #pragma unroll
    for (int r = 0; r < 16; r++) {
        const int row = r0 + r;
        const float v = (row < n) ? x[(size_t)row * D + c] : 0.0f;
        ((float*)&xs2[c][r >> 1])[r & 1] = v;
    }
    __syncthreads();

    ull aq[8], ak[8], av[8], aw[8];
    #pragma unroll
    for (int r = 0; r < 8; r++) { aq[r] = 0; ak[r] = 0; av[r] = 0; aw[r] = 0; }

    #pragma unroll 2
    for (int k = 0; k < D; k++) {
        const float wq = Wq[k * HC + c];
        const float wk = Wk[k * HC + c];
        const float wv = Wv[k * HC + c];
        const float ws = Ws[k * HC + c];
        const ull wq2 = pack2(wq, wq);
        const ull wk2 = pack2(wk, wk);
        const ull wv2 = pack2(wv, wv);
        const ull ws2 = pack2(ws, ws);
        #pragma unroll
        for (int r = 0; r < 8; r++) {
            const ull xv2 = *(const ull*)&xs2[k][r];
            aq[r] = ffma2(xv2, wq2, aq[r]);
            ak[r] = ffma2(xv2, wk2, ak[r]);
            av[r] = ffma2(xv2, wv2, av[r]);
            aw[r] = ffma2(xv2, ws2, aw[r]);
        }
    }
    const float bqv = bq[c], bkv = bk[c], bvv = bv[c], bsv = bs[c];
    #pragma unroll
    for (int r = 0; r < 8; r++) {
        float lo, hi;
        const int rowL = r0 + 2 * r, rowH = rowL + 1;
        unpack2(aq[r], lo, hi);
        if (rowL < n) g_q[(size_t)rowL * HC + c] = lo + bqv;
        if (rowH < n) g_q[(size_t)rowH * HC + c] = hi + bqv;
        unpack2(ak[r], lo, hi);
        if (rowL < n) g_k[(size_t)rowL * HC + c] = lo + bkv;
        if (rowH < n) g_k[(size_t)rowH * HC + c] = hi + bkv;
        unpack2(av[r], lo, hi);
        if (rowL < n) g_v[(size_t)rowL * HC + c] = lo + bvv;
        if (rowH < n) g_v[(size_t)rowH * HC + c] = hi + bvv;
        unpack2(aw[r], lo, hi);
        if (rowL < n) g_sk[(size_t)rowL * HC + c] = lo + bsv;
        if (rowH < n) g_sk[(size_t)rowH * HC + c] = hi + bsv;
    }
}

// ---------------------------------------------------------------------------
// K3: histogram of dst
// ---------------------------------------------------------------------------
__global__ void hist_kernel(const int* __restrict__ ei, int E) {
    int e = blockIdx.x * blockDim.x + threadIdx.x;
    if (e < E) atomicAdd(&g_cnt[ei[E + e]], 1);
}

// ---------------------------------------------------------------------------
// K2: mq[n, h, j] = sum_{c<64} We[j, 64h+c] * q[n, 64h+c]
// block = 192 threads (t = h*96 + j), 32 nodes per block.
// Full We staged once per block (coalesced); f32x2-packed inner loop.
// ---------------------------------------------------------------------------
__global__ __launch_bounds__(192) void mq_kernel(const float* __restrict__ We, int n) {
    __shared__ float We_s[2][96][65];
    __shared__ __align__(16) float qs[32][128];
    const int r0  = blockIdx.x * 32;
    const int tid = threadIdx.x;
    const int h   = tid / 96, j = tid % 96;   // warp-uniform h (96 = 3 warps)

    for (int i = tid; i < 96 * 128; i += 192) {
        const int jj = i >> 7, cc = i & 127;
        We_s[cc >> 6][jj][cc & 63] = We[jj * HC + cc];
    }
    for (int i = tid; i < 32 * 128; i += 192) {
        const int r = i >> 7, c = i & 127, row = r0 + r;
        qs[r][c] = (row < n) ? g_q[(size_t)row * HC + c] : 0.0f;
    }
    __syncthreads();

    ull wr2[32];
    #pragma unroll
    for (int i = 0; i < 32; i++)
        wr2[i] = pack2(We_s[h][j][2 * i], We_s[h][j][2 * i + 1]);

    #pragma unroll
    for (int pass = 0; pass < 2; pass++) {
        ull acc2[16];
        #pragma unroll
        for (int r = 0; r < 16; r++) acc2[r] = 0;
        #pragma unroll 4
        for (int i = 0; i < 32; i++) {
            const ull w2 = wr2[i];
            #pragma unroll
            for (int r = 0; r < 16; r++) {
                const ull q2 = *(const ull*)&qs[pass * 16 + r][64 * h + 2 * i];
                acc2[r] = ffma2(q2, w2, acc2[r]);
            }
        }
        #pragma unroll
        for (int r = 0; r < 16; r++) {
            float lo, hi; unpack2(acc2[r], lo, hi);
            const int row = r0 + pass * 16 + r;
            if (row < n) g_mq[(size_t)row * (2 * AD) + h * AD + j] = lo + hi;
        }
    }
}

// ---------------------------------------------------------------------------
// K4a: per-block sums of cnt
// ---------------------------------------------------------------------------
__global__ __launch_bounds__(1024) void scan_bsum_kernel(int n) {
    __shared__ int ws[32];
    const int i = blockIdx.x * 1024 + threadIdx.x;
    int v = (i < n) ? g_cnt[i] : 0;
    #pragma unroll
    for (int off = 16; off; off >>= 1) v += __shfl_xor_sync(~0u, v, off);
    if ((threadIdx.x & 31) == 0) ws[threadIdx.x >> 5] = v;
    __syncthreads();
    if (threadIdx.x < 32) {
        int s = ws[threadIdx.x];
        #pragma unroll
        for (int off = 16; off; off >>= 1) s += __shfl_xor_sync(~0u, s, off);
        if (threadIdx.x == 0) g_bsum[blockIdx.x] = s;
    }
}
// K4b: apply (each block sums preceding block sums itself)
__global__ __launch_bounds__(1024) void scan_apply_kernel(int n) {
    __shared__ int s[1024];
    const int tid = threadIdx.x;
    const int i = blockIdx.x * 1024 + tid;
    int base = 0;
    for (int b = 0; b < blockIdx.x; b++) base += g_bsum[b];
    const int v = (i < n) ? g_cnt[i] : 0;
    s[tid] = v;
    __syncthreads();
    #pragma unroll
    for (int off = 1; off < 1024; off <<= 1) {
        const int o = (tid >= off) ? s[tid - off] : 0;
        __syncthreads();
        s[tid] += o;
        __syncthreads();
    }
    if (i < n) g_cur[i] = base + s[tid] - v;
}

// ---------------------------------------------------------------------------
// K5: build sorted edge records (src, dst, time, eid)
// ---------------------------------------------------------------------------
__global__ void perm_kernel(const int* __restrict__ ei, const int* __restrict__ et, int E) {
    int e = blockIdx.x * blockDim.x + threadIdx.x;
    if (e < E) {
        const int s = ei[e], d = ei[E + e], t = et[e];
        const int pos = atomicAdd(&g_cur[d], 1);
        g_es[pos] = make_int4(s, d, t, e);
    }
}

// ---------------------------------------------------------------------------
// K6: edge kernel over dst-sorted records, 2 edges per iteration.
// ---------------------------------------------------------------------------
__global__ __launch_bounds__(256) void edge_kernel(
    const float* __restrict__ msg,  // [E,64]
    const float* __restrict__ Wt, const float* __restrict__ bt,
    float* __restrict__ out, int E)
{
    const int gw   = (blockIdx.x * blockDim.x + threadIdx.x) >> 5;
    const int lane = threadIdx.x & 31;
    int p = gw * CHUNK;
    if (p >= E) return;
    const int pend = min(p + CHUNK, E);

    const int  ll      = lane % 12;
    const bool is_a    = lane < 24;
    const bool a_head1 = (lane >= 12) && (lane < 24);
    const bool is_cos  = is_a && (ll < 4);

    float wt8[8], bt8[8];
    if (is_cos) {
        #pragma unroll
        for (int m = 0; m < 8; m++) { wt8[m] = Wt[8 * ll + m]; bt8[m] = bt[8 * ll + m]; }
    }

    int cur_dst = -1;
    float4 acc_v = make_float4(0, 0, 0, 0);
    float  accA[8] = {};
    float  den0 = 0.0f, den1 = 0.0f;

    auto flush = [&]() {
        if (cur_dst >= 0) {
            red_add_v4(out + (size_t)cur_dst * HC + 4 * lane, acc_v);
            if (is_a) {
                float* a = g_accA + (size_t)cur_dst * (2 * AD) + 8 * lane;
                red_add_v4(a,     make_float4(accA[0], accA[1], accA[2], accA[3]));
                red_add_v4(a + 4, make_float4(accA[4], accA[5], accA[6], accA[7]));
            }
            if (lane == 0)  atomicAdd(&g_den[cur_dst * 2],     den0);
            if (lane == 16) atomicAdd(&g_den[cur_dst * 2 + 1], den1);
            acc_v = make_float4(0, 0, 0, 0);
            #pragma unroll
            for (int m = 0; m < 8; m++) accA[m] = 0.0f;
            den0 = 0.0f; den1 = 0.0f;
        }
    };

    for (int pb = p; pb < pend; pb += 2) {
        const bool has1 = (pb + 1 < pend);
        const int4 m0 = g_es[pb];
        const int4 m1 = has1 ? g_es[pb + 1] : m0;
        const int s0 = m0.x, dA = m0.y, t0 = m0.z, e0 = m0.w;
        const int s1 = m1.x, dB = m1.y, t1 = m1.z, e1 = m1.w;

        // ---- issue all gathers up front (MLP) ----
        const float4 k40 = ((const float4*)(g_k + (size_t)s0 * HC))[lane];
        const float4 k41 = ((const float4*)(g_k + (size_t)s1 * HC))[lane];
        const float4 v40 = ((const float4*)(g_v + (size_t)s0 * HC))[lane];
        const float4 v41 = ((const float4*)(g_v + (size_t)s1 * HC))[lane];
        const float4 q40 = ((const float4*)(g_q + (size_t)dA * HC))[lane];
        const float4 q41 = ((const float4*)(g_q + (size_t)dB * HC))[lane];

        float mq0[8], mq1[8];
        if (is_a) {
            const float4 a0 = *(const float4*)(g_mq + (size_t)dA * (2 * AD) + 8 * lane);
            const float4 b0 = *(const float4*)(g_mq + (size_t)dA * (2 * AD) + 8 * lane + 4);
            const float4 a1 = *(const float4*)(g_mq + (size_t)dB * (2 * AD) + 8 * lane);
            const float4 b1 = *(const float4*)(g_mq + (size_t)dB * (2 * AD) + 8 * lane + 4);
            mq0[0]=a0.x; mq0[1]=a0.y; mq0[2]=a0.z; mq0[3]=a0.w;
            mq0[4]=b0.x; mq0[5]=b0.y; mq0[6]=b0.z; mq0[7]=b0.w;
            mq1[0]=a1.x; mq1[1]=a1.y; mq1[2]=a1.z; mq1[3]=a1.w;
            mq1[4]=b1.x; mq1[5]=b1.y; mq1[6]=b1.z; mq1[7]=b1.w;
        }

        // ---- attr slices ----
        float a80[8], a81[8];
        if (is_cos) {
            const float tf0 = (float)t0, tf1 = (float)t1;
            #pragma unroll
            for (int m = 0; m < 8; m++) {
                a80[m] = cosf(tf0 * wt8[m] + bt8[m]);
                a81[m] = cosf(tf1 * wt8[m] + bt8[m]);
            }
        } else if (is_a) {
            const float4 x00 = *(const float4*)(msg + (size_t)e0 * MD + 8 * (ll - 4));
            const float4 x01 = *(const float4*)(msg + (size_t)e0 * MD + 8 * (ll - 4) + 4);
            const float4 x10 = *(const float4*)(msg + (size_t)e1 * MD + 8 * (ll - 4));
            const float4 x11 = *(const float4*)(msg + (size_t)e1 * MD + 8 * (ll - 4) + 4);
            a80[0]=x00.x; a80[1]=x00.y; a80[2]=x00.z; a80[3]=x00.w;
            a80[4]=x01.x; a80[5]=x01.y; a80[6]=x01.z; a80[7]=x01.w;
            a81[0]=x10.x; a81[1]=x10.y; a81[2]=x10.z; a81[3]=x10.w;
            a81[4]=x11.x; a81[5]=x11.y; a81[6]=x11.z; a81[7]=x11.w;
        } else {
            #pragma unroll
            for (int m = 0; m < 8; m++) { a80[m] = 0.0f; a81[m] = 0.0f; }
        }

        // ---- alpha partials (4 interleaved reduce chains) ----
        const float qk0 = q40.x*k40.x + q40.y*k40.y + q40.z*k40.z + q40.w*k40.w;
        const float qk1 = q41.x*k41.x + q41.y*k41.y + q41.z*k41.z + q41.w*k41.w;
        float am0 = 0.0f, am1 = 0.0f;
        #pragma unroll
        for (int m = 0; m < 8; m++) { am0 += a80[m]*mq0[m]; am1 += a81[m]*mq1[m]; }

        float p00 = (lane < 16 ? qk0 : 0.0f) + ((is_a && !a_head1) ? am0 : 0.0f);
        float p01 = (lane >= 16 ? qk0 : 0.0f) + (a_head1 ? am0 : 0.0f);
        float p10 = (lane < 16 ? qk1 : 0.0f) + ((is_a && !a_head1) ? am1 : 0.0f);
        float p11 = (lane >= 16 ? qk1 : 0.0f) + (a_head1 ? am1 : 0.0f);
        #pragma unroll
        for (int off = 16; off; off >>= 1) {
            p00 += __shfl_xor_sync(~0u, p00, off);
            p01 += __shfl_xor_sync(~0u, p01, off);
            p10 += __shfl_xor_sync(~0u, p10, off);
            p11 += __shfl_xor_sync(~0u, p11, off);
        }
        const float w00 = __expf(0.125f * p00);
        const float w01 = __expf(0.125f * p01);
        const float w10 = __expf(0.125f * p10);
        const float w11 = __expf(0.125f * p11);

        // ---- accumulate edge 0 ----
        if (dA != cur_dst) { flush(); cur_dst = dA; }
        {
            const float wv = (lane < 16) ? w00 : w01;
            acc_v.x += wv * v40.x; acc_v.y += wv * v40.y;
            acc_v.z += wv * v40.z; acc_v.w += wv * v40.w;
            const float wa = a_head1 ? w01 : w00;
            #pragma unroll
            for (int m = 0; m < 8; m++) accA[m] += wa * a80[m];
            den0 += w00; den1 += w01;
        }
        // ---- accumulate edge 1 ----
        if (has1) {
            if (dB != cur_dst) { flush(); cur_dst = dB; }
            const float wv = (lane < 16) ? w10 : w11;
            acc_v.x += wv * v41.x; acc_v.y += wv * v41.y;
            acc_v.z += wv * v41.z; acc_v.w += wv * v41.w;
            const float wa = a_head1 ? w11 : w10;
            #pragma unroll
            for (int m = 0; m < 8; m++) accA[m] += wa * a81[m];
            den0 += w10; den1 += w11;
        }
    }
    flush();
}

// ---------------------------------------------------------------------------
// K7: out = (out_v + accA @ We_head) / den + skip   (16 rows per block)
// ---------------------------------------------------------------------------
__global__ __launch_bounds__(128) void final_kernel(
    const float* __restrict__ We, float* __restrict__ out, int n)
{
    __shared__ __align__(16) float aS[16][2 * AD];
    const int r0 = blockIdx.x * 16;
    const int c  = threadIdx.x;
    const int h  = c >> 6;

    for (int i = c; i < 16 * 2 * AD; i += 128) {
        const int r = i / (2 * AD), jj = i % (2 * AD), row = r0 + r;
        aS[r][jj] = (row < n) ? g_accA[(size_t)row * (2 * AD) + jj] : 0.0f;
    }
    __syncthreads();

    float acc[16] = {};
    #pragma unroll 4
    for (int j = 0; j < AD; j++) {
        const float wv = We[j * HC + c];
        #pragma unroll
        for (int r = 0; r < 16; r++) acc[r] += wv * aS[r][AD * h + j];
    }
    #pragma unroll
    for (int r = 0; r < 16; r++) {
        const int row = r0 + r;
        if (row < n) {
            const size_t o = (size_t)row * HC + c;
            const float den = g_den[row * 2 + h] + 1e-16f;
            out[o] = (out[o] + acc[r]) / den + g_sk[o];
        }
    }
}

// ---------------------------------------------------------------------------
extern "C" void kernel_launch(void* const* d_in, const int* in_sizes, int n_in,
                              void* d_out, int out_size)
{
    const float* x   = (const float*)d_in[0];
    const int*   ei  = (const int*)d_in[1];
    const int*   et  = (const int*)d_in[2];
    const float* msg = (const float*)d_in[3];
    const float* Wt  = (const float*)d_in[4];
    const float* bt  = (const float*)d_in[5];
    const float* Wq  = (const float*)d_in[6];
    const float* bq  = (const float*)d_in[7];
    const float* Wk  = (const float*)d_in[8];
    const float* bk  = (const float*)d_in[9];
    const float* Wv  = (const float*)d_in[10];
    const float* bv  = (const float*)d_in[11];
    const float* We  = (const float*)d_in[12];
    const float* Ws  = (const float*)d_in[13];
    const float* bs  = (const float*)d_in[14];
    float* out = (float*)d_out;

    const int N = in_sizes[0] / D;
    const int E = in_sizes[2];
    const int NB = (N + 1023) / 1024;

    zero_kernel<<<(N * 2 * AD + 255) / 256, 256>>>(N);
    proj_kernel<<<(N + 15) / 16, 128>>>(x, Wq, bq, Wk, bk, Wv, bv, Ws, bs, out, N);
    hist_kernel<<<(E + 255) / 256, 256>>>(ei, E);
    mq_kernel<<<(N + 31) / 32, 192>>>(We, N);   // captured profile slot
    scan_bsum_kernel<<<NB, 1024>>>(N);
    scan_apply_kernel<<<NB, 1024>>>(N);
    perm_kernel<<<(E + 255) / 256, 256>>>(ei, et, E);
    const int warps = (E + CHUNK - 1) / CHUNK;
    edge_kernel<<<(warps + 7) / 8, 256>>>(msg, Wt, bt, out, E);
    final_kernel<<<(N + 15) / 16, 128>>>(We, out, N);
}

// round 10
// speedup vs baseline: 1.1132x; 1.1132x over previous
#include <cuda_runtime.h>
#include <math.h>

#define D    128
#define HC   128
#define TD   32
#define MD   64
#define AD   96    // TD + MD
#define NMAX 50048
#define EMAX 500224
#define CHUNK 32   // sorted positions per warp

// scratch (static device memory — no allocations allowed)
__device__ float g_q[NMAX * HC];
__device__ float g_k[NMAX * HC];
__device__ float g_v[NMAX * HC];
__device__ float g_sk[NMAX * HC];
__device__ float g_mq[NMAX * 2 * AD];    // per-head We^T q
__device__ float g_accA[NMAX * 2 * AD];  // sum_e w_h * attr
__device__ float g_den[NMAX * 2];
__device__ int   g_cnt[NMAX];
__device__ int   g_cur[NMAX];
__device__ int4  g_es[EMAX];             // sorted (src, dst, time, eid)
__device__ int   g_bsum[64];

typedef unsigned long long ull;

__device__ __forceinline__ ull pack2(float lo, float hi) {
    ull r; asm("mov.b64 %0, {%1, %2};" : "=l"(r) : "f"(lo), "f"(hi)); return r;
}
__device__ __forceinline__ void unpack2(ull v, float& lo, float& hi) {
    asm("mov.b64 {%0, %1}, %2;" : "=f"(lo), "=f"(hi) : "l"(v));
}
__device__ __forceinline__ ull ffma2(ull a, ull b, ull c) {
    ull d; asm("fma.rn.f32x2 %0, %1, %2, %3;" : "=l"(d) : "l"(a), "l"(b), "l"(c)); return d;
}
__device__ __forceinline__ void red_add_v4(float* addr, float4 v) {
    asm volatile("red.global.add.v4.f32 [%0], {%1,%2,%3,%4};"
                 :: "l"(addr), "f"(v.x), "f"(v.y), "f"(v.z), "f"(v.w) : "memory");
}

// ---------------------------------------------------------------------------
// K0: zero accA + cnt
// ---------------------------------------------------------------------------
__global__ void zero_kernel(int n) {
    int i = blockIdx.x * blockDim.x + threadIdx.x;
    if (i < n * 2 * AD) g_accA[i] = 0.0f;
    if (i < n)          g_cnt[i] = 0;
}

// ---------------------------------------------------------------------------
// K1: fused node projections  q/k/v/skip = x @ W + b   (+ zero out/den)
// ---------------------------------------------------------------------------
__global__ __launch_bounds__(128) void proj_kernel(
    const float* __restrict__ x,
    const float* __restrict__ Wq, const float* __restrict__ bq,
    const float* __restrict__ Wk, const float* __restrict__ bk,
    const float* __restrict__ Wv, const float* __restrict__ bv,
    const float* __restrict__ Ws, const float* __restrict__ bs,
    float* __restrict__ out, int n)
{
    __shared__ __align__(16) float2 xs2[D][9];
    const int r0 = blockIdx.x * 16;
    const int c  = threadIdx.x;

    #pragma unroll
    for (int r = 0; r < 16; r++) {
        const int row = r0 + r;
        if (row < n) {
            out[(size_t)row * HC + c] = 0.0f;
            if (c < 2) g_den[row * 2 + c] = 0.0f;
        }
    }
    #pragma unroll
    for (int r = 0; r < 16; r++) {
        const int row = r0 + r;
        const float v = (row < n) ? x[(size_t)row * D + c] : 0.0f;
        ((float*)&xs2[c][r >> 1])[r & 1] = v;
    }
    __syncthreads();

    ull aq[8], ak[8], av[8], aw[8];
    #pragma unroll
    for (int r = 0; r < 8; r++) { aq[r] = 0; ak[r] = 0; av[r] = 0; aw[r] = 0; }

    #pragma unroll 2
    for (int k = 0; k < D; k++) {
        const float wq = Wq[k * HC + c];
        const float wk = Wk[k * HC + c];
        const float wv = Wv[k * HC + c];
        const float ws = Ws[k * HC + c];
        const ull wq2 = pack2(wq, wq);
        const ull wk2 = pack2(wk, wk);
        const ull wv2 = pack2(wv, wv);
        const ull ws2 = pack2(ws, ws);
        #pragma unroll
        for (int r = 0; r < 8; r++) {
            const ull xv2 = *(const ull*)&xs2[k][r];
            aq[r] = ffma2(xv2, wq2, aq[r]);
            ak[r] = ffma2(xv2, wk2, ak[r]);
            av[r] = ffma2(xv2, wv2, av[r]);
            aw[r] = ffma2(xv2, ws2, aw[r]);
        }
    }
    const float bqv = bq[c], bkv = bk[c], bvv = bv[c], bsv = bs[c];
    #pragma unroll
    for (int r = 0; r < 8; r++) {
        float lo, hi;
        const int rowL = r0 + 2 * r, rowH = rowL + 1;
        unpack2(aq[r], lo, hi);
        if (rowL < n) g_q[(size_t)rowL * HC + c] = lo + bqv;
        if (rowH < n) g_q[(size_t)rowH * HC + c] = hi + bqv;
        unpack2(ak[r], lo, hi);
        if (rowL < n) g_k[(size_t)rowL * HC + c] = lo + bkv;
        if (rowH < n) g_k[(size_t)rowH * HC + c] = hi + bkv;
        unpack2(av[r], lo, hi);
        if (rowL < n) g_v[(size_t)rowL * HC + c] = lo + bvv;
        if (rowH < n) g_v[(size_t)rowH * HC + c] = hi + bvv;
        unpack2(aw[r], lo, hi);
        if (rowL < n) g_sk[(size_t)rowL * HC + c] = lo + bsv;
        if (rowH < n) g_sk[(size_t)rowH * HC + c] = hi + bsv;
    }
}

// ---------------------------------------------------------------------------
// K3: histogram of dst
// ---------------------------------------------------------------------------
__global__ void hist_kernel(const int* __restrict__ ei, int E) {
    int e = blockIdx.x * blockDim.x + threadIdx.x;
    if (e < E) atomicAdd(&g_cnt[ei[E + e]], 1);
}

// ---------------------------------------------------------------------------
// K2: mq[n, h, j] = sum_{c<64} We[j, 64h+c] * q[n, 64h+c]
// block = 192 threads (t = h*96 + j), 32 nodes per block.
// Full We staged once per block; inner loop LDS.128 (2 ffma2 per load).
// ---------------------------------------------------------------------------
__global__ __launch_bounds__(192) void mq_kernel(const float* __restrict__ We, int n) {
    __shared__ float We_s[2][96][65];
    __shared__ __align__(16) float qs[32][128];
    const int r0  = blockIdx.x * 32;
    const int tid = threadIdx.x;
    const int h   = tid / 96, j = tid % 96;

    for (int i = tid; i < 96 * 128; i += 192) {
        const int jj = i >> 7, cc = i & 127;
        We_s[cc >> 6][jj][cc & 63] = We[jj * HC + cc];
    }
    for (int i = tid; i < 32 * 128; i += 192) {
        const int r = i >> 7, c = i & 127, row = r0 + r;
        qs[r][c] = (row < n) ? g_q[(size_t)row * HC + c] : 0.0f;
    }
    __syncthreads();

    ull wr2[32];
    #pragma unroll
    for (int i = 0; i < 32; i++)
        wr2[i] = pack2(We_s[h][j][2 * i], We_s[h][j][2 * i + 1]);

    #pragma unroll
    for (int pass = 0; pass < 2; pass++) {
        ull acc2[16];
        #pragma unroll
        for (int r = 0; r < 16; r++) acc2[r] = 0;
        #pragma unroll 2
        for (int i = 0; i < 16; i++) {            // 4 floats per step
            const ull w2a = wr2[2 * i], w2b = wr2[2 * i + 1];
            #pragma unroll
            for (int r = 0; r < 16; r++) {
                const ulonglong2 q4 =
                    *(const ulonglong2*)&qs[pass * 16 + r][64 * h + 4 * i];  // LDS.128
                acc2[r] = ffma2(q4.x, w2a, acc2[r]);
                acc2[r] = ffma2(q4.y, w2b, acc2[r]);
            }
        }
        #pragma unroll
        for (int r = 0; r < 16; r++) {
            float lo, hi; unpack2(acc2[r], lo, hi);
            const int row = r0 + pass * 16 + r;
            if (row < n) g_mq[(size_t)row * (2 * AD) + h * AD + j] = lo + hi;
        }
    }
}

// ---------------------------------------------------------------------------
// K4a: per-block sums of cnt
// ---------------------------------------------------------------------------
__global__ __launch_bounds__(1024) void scan_bsum_kernel(int n) {
    __shared__ int ws[32];
    const int i = blockIdx.x * 1024 + threadIdx.x;
    int v = (i < n) ? g_cnt[i] : 0;
    #pragma unroll
    for (int off = 16; off; off >>= 1) v += __shfl_xor_sync(~0u, v, off);
    if ((threadIdx.x & 31) == 0) ws[threadIdx.x >> 5] = v;
    __syncthreads();
    if (threadIdx.x < 32) {
        int s = ws[threadIdx.x];
        #pragma unroll
        for (int off = 16; off; off >>= 1) s += __shfl_xor_sync(~0u, s, off);
        if (threadIdx.x == 0) g_bsum[blockIdx.x] = s;
    }
}
// K4b: apply (each block sums preceding block sums itself)
__global__ __launch_bounds__(1024) void scan_apply_kernel(int n) {
    __shared__ int s[1024];
    const int tid = threadIdx.x;
    const int i = blockIdx.x * 1024 + tid;
    int base = 0;
    for (int b = 0; b < blockIdx.x; b++) base += g_bsum[b];
    const int v = (i < n) ? g_cnt[i] : 0;
    s[tid] = v;
    __syncthreads();
    #pragma unroll
    for (int off = 1; off < 1024; off <<= 1) {
        const int o = (tid >= off) ? s[tid - off] : 0;
        __syncthreads();
        s[tid] += o;
        __syncthreads();
    }
    if (i < n) g_cur[i] = base + s[tid] - v;
}

// ---------------------------------------------------------------------------
// K5: build sorted edge records (src, dst, time, eid)
// ---------------------------------------------------------------------------
__global__ void perm_kernel(const int* __restrict__ ei, const int* __restrict__ et, int E) {
    int e = blockIdx.x * blockDim.x + threadIdx.x;
    if (e < E) {
        const int s = ei[e], d = ei[E + e], t = et[e];
        const int pos = atomicAdd(&g_cur[d], 1);
        g_es[pos] = make_int4(s, d, t, e);
    }
}

// ---------------------------------------------------------------------------
// K6: edge kernel over dst-sorted records, 2 edges per iteration.
// ---------------------------------------------------------------------------
__global__ __launch_bounds__(256) void edge_kernel(
    const float* __restrict__ msg,  // [E,64]
    const float* __restrict__ Wt, const float* __restrict__ bt,
    float* __restrict__ out, int E)
{
    const int gw   = (blockIdx.x * blockDim.x + threadIdx.x) >> 5;
    const int lane = threadIdx.x & 31;
    int p = gw * CHUNK;
    if (p >= E) return;
    const int pend = min(p + CHUNK, E);

    const int  ll      = lane % 12;
    const bool is_a    = lane < 24;
    const bool a_head1 = (lane >= 12) && (lane < 24);
    const bool is_cos  = is_a && (ll < 4);

    float wt8[8], bt8[8];
    if (is_cos) {
        #pragma unroll
        for (int m = 0; m < 8; m++) { wt8[m] = Wt[8 * ll + m]; bt8[m] = bt[8 * ll + m]; }
    }

    int cur_dst = -1;
    float4 acc_v = make_float4(0, 0, 0, 0);
    float  accA[8] = {};
    float  den0 = 0.0f, den1 = 0.0f;

    auto flush = [&]() {
        if (cur_dst >= 0) {
            red_add_v4(out + (size_t)cur_dst * HC + 4 * lane, acc_v);
            if (is_a) {
                float* a = g_accA + (size_t)cur_dst * (2 * AD) + 8 * lane;
                red_add_v4(a,     make_float4(accA[0], accA[1], accA[2], accA[3]));
                red_add_v4(a + 4, make_float4(accA[4], accA[5], accA[6], accA[7]));
            }
            if (lane == 0)  atomicAdd(&g_den[cur_dst * 2],     den0);
            if (lane == 16) atomicAdd(&g_den[cur_dst * 2 + 1], den1);
            acc_v = make_float4(0, 0, 0, 0);
            #pragma unroll
            for (int m = 0; m < 8; m++) accA[m] = 0.0f;
            den0 = 0.0f; den1 = 0.0f;
        }
    };

    for (int pb = p; pb < pend; pb += 2) {
        const bool has1 = (pb + 1 < pend);
        const int4 m0 = g_es[pb];
        const int4 m1 = has1 ? g_es[pb + 1] : m0;
        const int s0 = m0.x, dA = m0.y, t0 = m0.z, e0 = m0.w;
        const int s1 = m1.x, dB = m1.y, t1 = m1.z, e1 = m1.w;

        // ---- issue all gathers up front (MLP) ----
        const float4 k40 = ((const float4*)(g_k + (size_t)s0 * HC))[lane];
        const float4 k41 = ((const float4*)(g_k + (size_t)s1 * HC))[lane];
        const float4 v40 = ((const float4*)(g_v + (size_t)s0 * HC))[lane];
        const float4 v41 = ((const float4*)(g_v + (size_t)s1 * HC))[lane];
        const float4 q40 = ((const float4*)(g_q + (size_t)dA * HC))[lane];
        const float4 q41 = ((const float4*)(g_q + (size_t)dB * HC))[lane];

        float mq0[8], mq1[8];
        if (is_a) {
            const float4 a0 = *(const float4*)(g_mq + (size_t)dA * (2 * AD) + 8 * lane);
            const float4 b0 = *(const float4*)(g_mq + (size_t)dA * (2 * AD) + 8 * lane + 4);
            const float4 a1 = *(const float4*)(g_mq + (size_t)dB * (2 * AD) + 8 * lane);
            const float4 b1 = *(const float4*)(g_mq + (size_t)dB * (2 * AD) + 8 * lane + 4);
            mq0[0]=a0.x; mq0[1]=a0.y; mq0[2]=a0.z; mq0[3]=a0.w;
            mq0[4]=b0.x; mq0[5]=b0.y; mq0[6]=b0.z; mq0[7]=b0.w;
            mq1[0]=a1.x; mq1[1]=a1.y; mq1[2]=a1.z; mq1[3]=a1.w;
            mq1[4]=b1.x; mq1[5]=b1.y; mq1[6]=b1.z; mq1[7]=b1.w;
        }

        // ---- attr slices ----
        float a80[8], a81[8];
        if (is_cos) {
            const float tf0 = (float)t0, tf1 = (float)t1;
            #pragma unroll
            for (int m = 0; m < 8; m++) {
                a80[m] = cosf(tf0 * wt8[m] + bt8[m]);
                a81[m] = cosf(tf1 * wt8[m] + bt8[m]);
            }
        } else if (is_a) {
            const float4 x00 = *(const float4*)(msg + (size_t)e0 * MD + 8 * (ll - 4));
            const float4 x01 = *(const float4*)(msg + (size_t)e0 * MD + 8 * (ll - 4) + 4);
            const float4 x10 = *(const float4*)(msg + (size_t)e1 * MD + 8 * (ll - 4));
            const float4 x11 = *(const float4*)(msg + (size_t)e1 * MD + 8 * (ll - 4) + 4);
            a80[0]=x00.x; a80[1]=x00.y; a80[2]=x00.z; a80[3]=x00.w;
            a80[4]=x01.x; a80[5]=x01.y; a80[6]=x01.z; a80[7]=x01.w;
            a81[0]=x10.x; a81[1]=x10.y; a81[2]=x10.z; a81[3]=x10.w;
            a81[4]=x11.x; a81[5]=x11.y; a81[6]=x11.z; a81[7]=x11.w;
        } else {
            #pragma unroll
            for (int m = 0; m < 8; m++) { a80[m] = 0.0f; a81[m] = 0.0f; }
        }

        // ---- alpha partials (4 interleaved reduce chains) ----
        const float qk0 = q40.x*k40.x + q40.y*k40.y + q40.z*k40.z + q40.w*k40.w;
        const float qk1 = q41.x*k41.x + q41.y*k41.y + q41.z*k41.z + q41.w*k41.w;
        float am0 = 0.0f, am1 = 0.0f;
        #pragma unroll
        for (int m = 0; m < 8; m++) { am0 += a80[m]*mq0[m]; am1 += a81[m]*mq1[m]; }

        float p00 = (lane < 16 ? qk0 : 0.0f) + ((is_a && !a_head1) ? am0 : 0.0f);
        float p01 = (lane >= 16 ? qk0 : 0.0f) + (a_head1 ? am0 : 0.0f);
        float p10 = (lane < 16 ? qk1 : 0.0f) + ((is_a && !a_head1) ? am1 : 0.0f);
        float p11 = (lane >= 16 ? qk1 : 0.0f) + (a_head1 ? am1 : 0.0f);
        #pragma unroll
        for (int off = 16; off; off >>= 1) {
            p00 += __shfl_xor_sync(~0u, p00, off);
            p01 += __shfl_xor_sync(~0u, p01, off);
            p10 += __shfl_xor_sync(~0u, p10, off);
            p11 += __shfl_xor_sync(~0u, p11, off);
        }
        const float w00 = __expf(0.125f * p00);
        const float w01 = __expf(0.125f * p01);
        const float w10 = __expf(0.125f * p10);
        const float w11 = __expf(0.125f * p11);

        // ---- accumulate edge 0 ----
        if (dA != cur_dst) { flush(); cur_dst = dA; }
        {
            const float wv = (lane < 16) ? w00 : w01;
            acc_v.x += wv * v40.x; acc_v.y += wv * v40.y;
            acc_v.z += wv * v40.z; acc_v.w += wv * v40.w;
            const float wa = a_head1 ? w01 : w00;
            #pragma unroll
            for (int m = 0; m < 8; m++) accA[m] += wa * a80[m];
            den0 += w00; den1 += w01;
        }
        // ---- accumulate edge 1 ----
        if (has1) {
            if (dB != cur_dst) { flush(); cur_dst = dB; }
            const float wv = (lane < 16) ? w10 : w11;
            acc_v.x += wv * v41.x; acc_v.y += wv * v41.y;
            acc_v.z += wv * v41.z; acc_v.w += wv * v41.w;
            const float wa = a_head1 ? w11 : w10;
            #pragma unroll
            for (int m = 0; m < 8; m++) accA[m] += wa * a81[m];
            den0 += w10; den1 += w11;
        }
    }
    flush();
}

// ---------------------------------------------------------------------------
// K7: out = (out_v + accA @ We_head) / den + skip   (8 rows per block)
// ---------------------------------------------------------------------------
__global__ __launch_bounds__(128) void final_kernel(
    const float* __restrict__ We, float* __restrict__ out, int n)
{
    __shared__ __align__(16) float aS[8][2 * AD];
    const int r0 = blockIdx.x * 8;
    const int c  = threadIdx.x;
    const int h  = c >> 6;

    for (int i = c; i < 8 * 2 * AD; i += 128) {
        const int r = i / (2 * AD), jj = i % (2 * AD), row = r0 + r;
        aS[r][jj] = (row < n) ? g_accA[(size_t)row * (2 * AD) + jj] : 0.0f;
    }
    __syncthreads();

    float acc[8] = {};
    #pragma unroll 4
    for (int j = 0; j < AD; j++) {
        const float wv = We[j * HC + c];
        #pragma unroll
        for (int r = 0; r < 8; r++) acc[r] += wv * aS[r][AD * h + j];
    }
    #pragma unroll
    for (int r = 0; r < 8; r++) {
        const int row = r0 + r;
        if (row < n) {
            const size_t o = (size_t)row * HC + c;
            const float den = g_den[row * 2 + h] + 1e-16f;
            out[o] = (out[o] + acc[r]) / den + g_sk[o];
        }
    }
}

// ---------------------------------------------------------------------------
extern "C" void kernel_launch(void* const* d_in, const int* in_sizes, int n_in,
                              void* d_out, int out_size)
{
    const float* x   = (const float*)d_in[0];
    const int*   ei  = (const int*)d_in[1];
    const int*   et  = (const int*)d_in[2];
    const float* msg = (const float*)d_in[3];
    const float* Wt  = (const float*)d_in[4];
    const float* bt  = (const float*)d_in[5];
    const float* Wq  = (const float*)d_in[6];
    const float* bq  = (const float*)d_in[7];
    const float* Wk  = (const float*)d_in[8];
    const float* bk  = (const float*)d_in[9];
    const float* Wv  = (const float*)d_in[10];
    const float* bv  = (const float*)d_in[11];
    const float* We  = (const float*)d_in[12];
    const float* Ws  = (const float*)d_in[13];
    const float* bs  = (const float*)d_in[14];
    float* out = (float*)d_out;

    const int N = in_sizes[0] / D;
    const int E = in_sizes[2];
    const int NB = (N + 1023) / 1024;

    zero_kernel<<<(N * 2 * AD + 255) / 256, 256>>>(N);
    proj_kernel<<<(N + 15) / 16, 128>>>(x, Wq, bq, Wk, bk, Wv, bv, Ws, bs, out, N);
    hist_kernel<<<(E + 255) / 256, 256>>>(ei, E);
    mq_kernel<<<(N + 31) / 32, 192>>>(We, N);   // captured profile slot
    scan_bsum_kernel<<<NB, 1024>>>(N);
    scan_apply_kernel<<<NB, 1024>>>(N);
    perm_kernel<<<(E + 255) / 256, 256>>>(ei, et, E);
    const int warps = (E + CHUNK - 1) / CHUNK;
    edge_kernel<<<(warps + 7) / 8, 256>>>(msg, Wt, bt, out, E);
    final_kernel<<<(N + 7) / 8, 128>>>(We, out, N);
}

// round 11
// speedup vs baseline: 1.1318x; 1.0167x over previous
#include <cuda_runtime.h>
#include <math.h>

#define D    128
#define HC   128
#define TD   32
#define MD   64
#define AD   96    // TD + MD
#define NMAX 50048
#define EMAX 500224
#define CHUNK 16   // sorted positions per warp

// scratch (static device memory — no allocations allowed)
__device__ float g_q[NMAX * HC];
__device__ float g_k[NMAX * HC];
__device__ float g_v[NMAX * HC];
__device__ float g_sk[NMAX * HC];
__device__ float g_mq[NMAX * 2 * AD];    // per-head We^T q
__device__ float g_accA[NMAX * 2 * AD];  // sum_e w_h * attr
__device__ float g_den[NMAX * 2];
__device__ int   g_cnt[NMAX];
__device__ int   g_cur[NMAX];
__device__ int4  g_es[EMAX];             // sorted (src, dst, time, eid)
__device__ int   g_bsum[64];

typedef unsigned long long ull;

__device__ __forceinline__ ull pack2(float lo, float hi) {
    ull r; asm("mov.b64 %0, {%1, %2};" : "=l"(r) : "f"(lo), "f"(hi)); return r;
}
__device__ __forceinline__ void unpack2(ull v, float& lo, float& hi) {
    asm("mov.b64 {%0, %1}, %2;" : "=f"(lo), "=f"(hi) : "l"(v));
}
__device__ __forceinline__ ull ffma2(ull a, ull b, ull c) {
    ull d; asm("fma.rn.f32x2 %0, %1, %2, %3;" : "=l"(d) : "l"(a), "l"(b), "l"(c)); return d;
}
__device__ __forceinline__ void red_add_v4(float* addr, float4 v) {
    asm volatile("red.global.add.v4.f32 [%0], {%1,%2,%3,%4};"
                 :: "l"(addr), "f"(v.x), "f"(v.y), "f"(v.z), "f"(v.w) : "memory");
}

// ---------------------------------------------------------------------------
// K0: zero accA + cnt
// ---------------------------------------------------------------------------
__global__ void zero_kernel(int n) {
    int i = blockIdx.x * blockDim.x + threadIdx.x;
    if (i < n * 2 * AD) g_accA[i] = 0.0f;
    if (i < n)          g_cnt[i] = 0;
}

// ---------------------------------------------------------------------------
// K1: fused node projections  q/k/v/skip = x @ W + b   (+ zero out/den)
// Weights double-buffered through smem in 8-k tiles (batched LDG prefetch).
// ---------------------------------------------------------------------------
__global__ __launch_bounds__(128) void proj_kernel(
    const float* __restrict__ x,
    const float* __restrict__ Wq, const float* __restrict__ bq,
    const float* __restrict__ Wk, const float* __restrict__ bk,
    const float* __restrict__ Wv, const float* __restrict__ bv,
    const float* __restrict__ Ws, const float* __restrict__ bs,
    float* __restrict__ out, int n)
{
    __shared__ __align__(16) float2 xs2[D][9];
    __shared__ float Wt_s[2][8][4][HC];   // [buf][kk][w][c]  2 x 16KB
    const int r0 = blockIdx.x * 16;
    const int c  = threadIdx.x;

    #pragma unroll
    for (int r = 0; r < 16; r++) {
        const int row = r0 + r;
        if (row < n) {
            out[(size_t)row * HC + c] = 0.0f;
            if (c < 2) g_den[row * 2 + c] = 0.0f;
        }
    }
    #pragma unroll
    for (int r = 0; r < 16; r++) {
        const int row = r0 + r;
        const float v = (row < n) ? x[(size_t)row * D + c] : 0.0f;
        ((float*)&xs2[c][r >> 1])[r & 1] = v;
    }

    auto stage = [&](int t, int b) {
        const int k0 = t * 8;
        #pragma unroll
        for (int kk = 0; kk < 8; kk++) {
            Wt_s[b][kk][0][c] = Wq[(k0 + kk) * HC + c];
            Wt_s[b][kk][1][c] = Wk[(k0 + kk) * HC + c];
            Wt_s[b][kk][2][c] = Wv[(k0 + kk) * HC + c];
            Wt_s[b][kk][3][c] = Ws[(k0 + kk) * HC + c];
        }
    };

    stage(0, 0);
    __syncthreads();

    ull aq[8], ak[8], av[8], aw[8];
    #pragma unroll
    for (int r = 0; r < 8; r++) { aq[r] = 0; ak[r] = 0; av[r] = 0; aw[r] = 0; }

    for (int t = 0; t < 16; t++) {
        const int b = t & 1;
        if (t + 1 < 16) stage(t + 1, b ^ 1);
        #pragma unroll
        for (int kk = 0; kk < 8; kk++) {
            const int k = t * 8 + kk;
            const float wq = Wt_s[b][kk][0][c];
            const float wk = Wt_s[b][kk][1][c];
            const float wv = Wt_s[b][kk][2][c];
            const float ws = Wt_s[b][kk][3][c];
            const ull wq2 = pack2(wq, wq);
            const ull wk2 = pack2(wk, wk);
            const ull wv2 = pack2(wv, wv);
            const ull ws2 = pack2(ws, ws);
            #pragma unroll
            for (int r = 0; r < 8; r++) {
                const ull xv2 = *(const ull*)&xs2[k][r];
                aq[r] = ffma2(xv2, wq2, aq[r]);
                ak[r] = ffma2(xv2, wk2, ak[r]);
                av[r] = ffma2(xv2, wv2, av[r]);
                aw[r] = ffma2(xv2, ws2, aw[r]);
            }
        }
        __syncthreads();
    }

    const float bqv = bq[c], bkv = bk[c], bvv = bv[c], bsv = bs[c];
    #pragma unroll
    for (int r = 0; r < 8; r++) {
        float lo, hi;
        const int rowL = r0 + 2 * r, rowH = rowL + 1;
        unpack2(aq[r], lo, hi);
        if (rowL < n) g_q[(size_t)rowL * HC + c] = lo + bqv;
        if (rowH < n) g_q[(size_t)rowH * HC + c] = hi + bqv;
        unpack2(ak[r], lo, hi);
        if (rowL < n) g_k[(size_t)rowL * HC + c] = lo + bkv;
        if (rowH < n) g_k[(size_t)rowH * HC + c] = hi + bkv;
        unpack2(av[r], lo, hi);
        if (rowL < n) g_v[(size_t)rowL * HC + c] = lo + bvv;
        if (rowH < n) g_v[(size_t)rowH * HC + c] = hi + bvv;
        unpack2(aw[r], lo, hi);
        if (rowL < n) g_sk[(size_t)rowL * HC + c] = lo + bsv;
        if (rowH < n) g_sk[(size_t)rowH * HC + c] = hi + bsv;
    }
}

// ---------------------------------------------------------------------------
// K3: histogram of dst
// ---------------------------------------------------------------------------
__global__ void hist_kernel(const int* __restrict__ ei, int E) {
    int e = blockIdx.x * blockDim.x + threadIdx.x;
    if (e < E) atomicAdd(&g_cnt[ei[E + e]], 1);
}

// ---------------------------------------------------------------------------
// K2: mq[n, h, j] = sum_{c<64} We[j, 64h+c] * q[n, 64h+c]
// ---------------------------------------------------------------------------
__global__ __launch_bounds__(192) void mq_kernel(const float* __restrict__ We, int n) {
    __shared__ float We_s[2][96][65];
    __shared__ __align__(16) float qs[32][128];
    const int r0  = blockIdx.x * 32;
    const int tid = threadIdx.x;
    const int h   = tid / 96, j = tid % 96;

    for (int i = tid; i < 96 * 128; i += 192) {
        const int jj = i >> 7, cc = i & 127;
        We_s[cc >> 6][jj][cc & 63] = We[jj * HC + cc];
    }
    for (int i = tid; i < 32 * 128; i += 192) {
        const int r = i >> 7, c = i & 127, row = r0 + r;
        qs[r][c] = (row < n) ? g_q[(size_t)row * HC + c] : 0.0f;
    }
    __syncthreads();

    ull wr2[32];
    #pragma unroll
    for (int i = 0; i < 32; i++)
        wr2[i] = pack2(We_s[h][j][2 * i], We_s[h][j][2 * i + 1]);

    #pragma unroll
    for (int pass = 0; pass < 2; pass++) {
        ull acc2[16];
        #pragma unroll
        for (int r = 0; r < 16; r++) acc2[r] = 0;
        #pragma unroll 2
        for (int i = 0; i < 16; i++) {
            const ull w2a = wr2[2 * i], w2b = wr2[2 * i + 1];
            #pragma unroll
            for (int r = 0; r < 16; r++) {
                const ulonglong2 q4 =
                    *(const ulonglong2*)&qs[pass * 16 + r][64 * h + 4 * i];
                acc2[r] = ffma2(q4.x, w2a, acc2[r]);
                acc2[r] = ffma2(q4.y, w2b, acc2[r]);
            }
        }
        #pragma unroll
        for (int r = 0; r < 16; r++) {
            float lo, hi; unpack2(acc2[r], lo, hi);
            const int row = r0 + pass * 16 + r;
            if (row < n) g_mq[(size_t)row * (2 * AD) + h * AD + j] = lo + hi;
        }
    }
}

// ---------------------------------------------------------------------------
// K4a: per-block sums of cnt
// ---------------------------------------------------------------------------
__global__ __launch_bounds__(1024) void scan_bsum_kernel(int n) {
    __shared__ int ws[32];
    const int i = blockIdx.x * 1024 + threadIdx.x;
    int v = (i < n) ? g_cnt[i] : 0;
    #pragma unroll
    for (int off = 16; off; off >>= 1) v += __shfl_xor_sync(~0u, v, off);
    if ((threadIdx.x & 31) == 0) ws[threadIdx.x >> 5] = v;
    __syncthreads();
    if (threadIdx.x < 32) {
        int s = ws[threadIdx.x];
        #pragma unroll
        for (int off = 16; off; off >>= 1) s += __shfl_xor_sync(~0u, s, off);
        if (threadIdx.x == 0) g_bsum[blockIdx.x] = s;
    }
}
// K4b: apply (each block sums preceding block sums itself)
__global__ __launch_bounds__(1024) void scan_apply_kernel(int n) {
    __shared__ int s[1024];
    const int tid = threadIdx.x;
    const int i = blockIdx.x * 1024 + tid;
    int base = 0;
    for (int b = 0; b < blockIdx.x; b++) base += g_bsum[b];
    const int v = (i < n) ? g_cnt[i] : 0;
    s[tid] = v;
    __syncthreads();
    #pragma unroll
    for (int off = 1; off < 1024; off <<= 1) {
        const int o = (tid >= off) ? s[tid - off] : 0;
        __syncthreads();
        s[tid] += o;
        __syncthreads();
    }
    if (i < n) g_cur[i] = base + s[tid] - v;
}

// ---------------------------------------------------------------------------
// K5: build sorted edge records (src, dst, time, eid)
// ---------------------------------------------------------------------------
__global__ void perm_kernel(const int* __restrict__ ei, const int* __restrict__ et, int E) {
    int e = blockIdx.x * blockDim.x + threadIdx.x;
    if (e < E) {
        const int s = ei[e], d = ei[E + e], t = et[e];
        const int pos = atomicAdd(&g_cur[d], 1);
        g_es[pos] = make_int4(s, d, t, e);
    }
}

// ---------------------------------------------------------------------------
// K6: edge kernel over dst-sorted records, 2 edges per iteration.
// ---------------------------------------------------------------------------
__global__ __launch_bounds__(256) void edge_kernel(
    const float* __restrict__ msg,  // [E,64]
    const float* __restrict__ Wt, const float* __restrict__ bt,
    float* __restrict__ out, int E)
{
    const int gw   = (blockIdx.x * blockDim.x + threadIdx.x) >> 5;
    const int lane = threadIdx.x & 31;
    int p = gw * CHUNK;
    if (p >= E) return;
    const int pend = min(p + CHUNK, E);

    const int  ll      = lane % 12;
    const bool is_a    = lane < 24;
    const bool a_head1 = (lane >= 12) && (lane < 24);
    const bool is_cos  = is_a && (ll < 4);

    float wt8[8], bt8[8];
    if (is_cos) {
        #pragma unroll
        for (int m = 0; m < 8; m++) { wt8[m] = Wt[8 * ll + m]; bt8[m] = bt[8 * ll + m]; }
    }

    int cur_dst = -1;
    float4 acc_v = make_float4(0, 0, 0, 0);
    float  accA[8] = {};
    float  den0 = 0.0f, den1 = 0.0f;

    auto flush = [&]() {
        if (cur_dst >= 0) {
            red_add_v4(out + (size_t)cur_dst * HC + 4 * lane, acc_v);
            if (is_a) {
                float* a = g_accA + (size_t)cur_dst * (2 * AD) + 8 * lane;
                red_add_v4(a,     make_float4(accA[0], accA[1], accA[2], accA[3]));
                red_add_v4(a + 4, make_float4(accA[4], accA[5], accA[6], accA[7]));
            }
            if (lane == 0)  atomicAdd(&g_den[cur_dst * 2],     den0);
            if (lane == 16) atomicAdd(&g_den[cur_dst * 2 + 1], den1);
            acc_v = make_float4(0, 0, 0, 0);
            #pragma unroll
            for (int m = 0; m < 8; m++) accA[m] = 0.0f;
            den0 = 0.0f; den1 = 0.0f;
        }
    };

    for (int pb = p; pb < pend; pb += 2) {
        const bool has1 = (pb + 1 < pend);
        const int4 m0 = g_es[pb];
        const int4 m1 = has1 ? g_es[pb + 1] : m0;
        const int s0 = m0.x, dA = m0.y, t0 = m0.z, e0 = m0.w;
        const int s1 = m1.x, dB = m1.y, t1 = m1.z, e1 = m1.w;

        // ---- issue all gathers up front (MLP) ----
        const float4 k40 = ((const float4*)(g_k + (size_t)s0 * HC))[lane];
        const float4 k41 = ((const float4*)(g_k + (size_t)s1 * HC))[lane];
        const float4 v40 = ((const float4*)(g_v + (size_t)s0 * HC))[lane];
        const float4 v41 = ((const float4*)(g_v + (size_t)s1 * HC))[lane];
        const float4 q40 = ((const float4*)(g_q + (size_t)dA * HC))[lane];
        const float4 q41 = ((const float4*)(g_q + (size_t)dB * HC))[lane];

        float mq0[8], mq1[8];
        if (is_a) {
            const float4 a0 = *(const float4*)(g_mq + (size_t)dA * (2 * AD) + 8 * lane);
            const float4 b0 = *(const float4*)(g_mq + (size_t)dA * (2 * AD) + 8 * lane + 4);
            const float4 a1 = *(const float4*)(g_mq + (size_t)dB * (2 * AD) + 8 * lane);
            const float4 b1 = *(const float4*)(g_mq + (size_t)dB * (2 * AD) + 8 * lane + 4);
            mq0[0]=a0.x; mq0[1]=a0.y; mq0[2]=a0.z; mq0[3]=a0.w;
            mq0[4]=b0.x; mq0[5]=b0.y; mq0[6]=b0.z; mq0[7]=b0.w;
            mq1[0]=a1.x; mq1[1]=a1.y; mq1[2]=a1.z; mq1[3]=a1.w;
            mq1[4]=b1.x; mq1[5]=b1.y; mq1[6]=b1.z; mq1[7]=b1.w;
        }

        // ---- attr slices ----
        float a80[8], a81[8];
        if (is_cos) {
            const float tf0 = (float)t0, tf1 = (float)t1;
            #pragma unroll
            for (int m = 0; m < 8; m++) {
                a80[m] = cosf(tf0 * wt8[m] + bt8[m]);
                a81[m] = cosf(tf1 * wt8[m] + bt8[m]);
            }
        } else if (is_a) {
            const float4 x00 = *(const float4*)(msg + (size_t)e0 * MD + 8 * (ll - 4));
            const float4 x01 = *(const float4*)(msg + (size_t)e0 * MD + 8 * (ll - 4) + 4);
            const float4 x10 = *(const float4*)(msg + (size_t)e1 * MD + 8 * (ll - 4));
            const float4 x11 = *(const float4*)(msg + (size_t)e1 * MD + 8 * (ll - 4) + 4);
            a80[0]=x00.x; a80[1]=x00.y; a80[2]=x00.z; a80[3]=x00.w;
            a80[4]=x01.x; a80[5]=x01.y; a80[6]=x01.z; a80[7]=x01.w;
            a81[0]=x10.x; a81[1]=x10.y; a81[2]=x10.z; a81[3]=x10.w;
            a81[4]=x11.x; a81[5]=x11.y; a81[6]=x11.z; a81[7]=x11.w;
        } else {
            #pragma unroll
            for (int m = 0; m < 8; m++) { a80[m] = 0.0f; a81[m] = 0.0f; }
        }

        // ---- alpha partials (4 interleaved reduce chains) ----
        const float qk0 = q40.x*k40.x + q40.y*k40.y + q40.z*k40.z + q40.w*k40.w;
        const float qk1 = q41.x*k41.x + q41.y*k41.y + q41.z*k41.z + q41.w*k41.w;
        float am0 = 0.0f, am1 = 0.0f;
        #pragma unroll
        for (int m = 0; m < 8; m++) { am0 += a80[m]*mq0[m]; am1 += a81[m]*mq1[m]; }

        float p00 = (lane < 16 ? qk0 : 0.0f) + ((is_a && !a_head1) ? am0 : 0.0f);
        float p01 = (lane >= 16 ? qk0 : 0.0f) + (a_head1 ? am0 : 0.0f);
        float p10 = (lane < 16 ? qk1 : 0.0f) + ((is_a && !a_head1) ? am1 : 0.0f);
        float p11 = (lane >= 16 ? qk1 : 0.0f) + (a_head1 ? am1 : 0.0f);
        #pragma unroll
        for (int off = 16; off; off >>= 1) {
            p00 += __shfl_xor_sync(~0u, p00, off);
            p01 += __shfl_xor_sync(~0u, p01, off);
            p10 += __shfl_xor_sync(~0u, p10, off);
            p11 += __shfl_xor_sync(~0u, p11, off);
        }
        const float w00 = __expf(0.125f * p00);
        const float w01 = __expf(0.125f * p01);
        const float w10 = __expf(0.125f * p10);
        const float w11 = __expf(0.125f * p11);

        // ---- accumulate edge 0 ----
        if (dA != cur_dst) { flush(); cur_dst = dA; }
        {
            const float wv = (lane < 16) ? w00 : w01;
            acc_v.x += wv * v40.x; acc_v.y += wv * v40.y;
            acc_v.z += wv * v40.z; acc_v.w += wv * v40.w;
            const float wa = a_head1 ? w01 : w00;
            #pragma unroll
            for (int m = 0; m < 8; m++) accA[m] += wa * a80[m];
            den0 += w00; den1 += w01;
        }
        // ---- accumulate edge 1 ----
        if (has1) {
            if (dB != cur_dst) { flush(); cur_dst = dB; }
            const float wv = (lane < 16) ? w10 : w11;
            acc_v.x += wv * v41.x; acc_v.y += wv * v41.y;
            acc_v.z += wv * v41.z; acc_v.w += wv * v41.w;
            const float wa = a_head1 ? w11 : w10;
            #pragma unroll
            for (int m = 0; m < 8; m++) accA[m] += wa * a81[m];
            den0 += w10; den1 += w11;
        }
    }
    flush();
}

// ---------------------------------------------------------------------------
// K7: out = (out_v + accA @ We_head) / den + skip   (8 rows per block)
// ---------------------------------------------------------------------------
__global__ __launch_bounds__(128) void final_kernel(
    const float* __restrict__ We, float* __restrict__ out, int n)
{
    __shared__ __align__(16) float aS[8][2 * AD];
    const int r0 = blockIdx.x * 8;
    const int c  = threadIdx.x;
    const int h  = c >> 6;

    for (int i = c; i < 8 * 2 * AD; i += 128) {
        const int r = i / (2 * AD), jj = i % (2 * AD), row = r0 + r;
        aS[r][jj] = (row < n) ? g_accA[(size_t)row * (2 * AD) + jj] : 0.0f;
    }
    __syncthreads();

    float acc[8] = {};
    #pragma unroll 4
    for (int j = 0; j < AD; j++) {
        const float wv = We[j * HC + c];
        #pragma unroll
        for (int r = 0; r < 8; r++) acc[r] += wv * aS[r][AD * h + j];
    }
    #pragma unroll
    for (int r = 0; r < 8; r++) {
        const int row = r0 + r;
        if (row < n) {
            const size_t o = (size_t)row * HC + c;
            const float den = g_den[row * 2 + h] + 1e-16f;
            out[o] = (out[o] + acc[r]) / den + g_sk[o];
        }
    }
}

// ---------------------------------------------------------------------------
extern "C" void kernel_launch(void* const* d_in, const int* in_sizes, int n_in,
                              void* d_out, int out_size)
{
    const float* x   = (const float*)d_in[0];
    const int*   ei  = (const int*)d_in[1];
    const int*   et  = (const int*)d_in[2];
    const float* msg = (const float*)d_in[3];
    const float* Wt  = (const float*)d_in[4];
    const float* bt  = (const float*)d_in[5];
    const float* Wq  = (const float*)d_in[6];
    const float* bq  = (const float*)d_in[7];
    const float* Wk  = (const float*)d_in[8];
    const float* bk  = (const float*)d_in[9];
    const float* Wv  = (const float*)d_in[10];
    const float* bv  = (const float*)d_in[11];
    const float* We  = (const float*)d_in[12];
    const float* Ws  = (const float*)d_in[13];
    const float* bs  = (const float*)d_in[14];
    float* out = (float*)d_out;

    const int N = in_sizes[0] / D;
    const int E = in_sizes[2];
    const int NB = (N + 1023) / 1024;

    zero_kernel<<<(N * 2 * AD + 255) / 256, 256>>>(N);
    proj_kernel<<<(N + 15) / 16, 128>>>(x, Wq, bq, Wk, bk, Wv, bv, Ws, bs, out, N);
    hist_kernel<<<(E + 255) / 256, 256>>>(ei, E);
    mq_kernel<<<(N + 31) / 32, 192>>>(We, N);
    scan_bsum_kernel<<<NB, 1024>>>(N);
    scan_apply_kernel<<<NB, 1024>>>(N);
    perm_kernel<<<(E + 255) / 256, 256>>>(ei, et, E);
    const int warps = (E + CHUNK - 1) / CHUNK;
    edge_kernel<<<(warps + 7) / 8, 256>>>(msg, Wt, bt, out, E);
    final_kernel<<<(N + 7) / 8, 128>>>(We, out, N);
}